// round 2
// baseline (speedup 1.0000x reference)
#include <cuda_runtime.h>
#include <cuda_bf16.h>

// Problem constants (fixed by the dataset).
#define NN 50000
#define EE 800000
#define HH 256

// ---------------------------------------------------------------------------
// Device scratch (static allocation; no cudaMalloc allowed)
// ---------------------------------------------------------------------------
__device__ int   g_deg[NN];
__device__ int   g_cursor[NN];
__device__ int   g_rowptr[NN + 1];
__device__ int   g_colidx[EE];
__device__ int   g_bsums[64];
__device__ int   g_maxdeg;
__device__ float g_diag[NN];
__device__ float g_negscale;
__device__ float g_T[(size_t)NN * HH];    // tx1 scratch (H channels)
__device__ float g_H[(size_t)NN * HH];    // hidden scratch
__device__ float g_T3[(size_t)NN * 3];    // tx1 scratch (3 channels, input layer)

// ---------------------------------------------------------------------------
// Setup kernels: degree, lambda_max, coefficients, CSR build
// ---------------------------------------------------------------------------
__global__ void zero_k() {
    int i = blockIdx.x * blockDim.x + threadIdx.x;
    if (i < NN) { g_deg[i] = 0; g_cursor[i] = 0; }
    if (i == 0) g_maxdeg = 0;
}

__global__ void degree_k(const int* __restrict__ row) {
    int e = blockIdx.x * blockDim.x + threadIdx.x;
    if (e < EE) atomicAdd(&g_deg[row[e]], 1);
}

__global__ void maxdeg_k() {
    int i = blockIdx.x * blockDim.x + threadIdx.x;
    if (i < NN) atomicMax(&g_maxdeg, g_deg[i]);
}

__global__ void coeff_k() {
    int i = blockIdx.x * blockDim.x + threadIdx.x;
    if (i < NN) {
        float md    = (float)g_maxdeg;
        float lam   = 2.0f * md;
        float scale = 2.0f / lam;
        g_diag[i]   = scale * (float)g_deg[i] - 1.0f;
        if (i == 0) g_negscale = -scale;
    }
}

#define SCAN_B 1024
__global__ void scan_block_k() {
    __shared__ int sh[SCAN_B];
    int tid = threadIdx.x;
    int i = blockIdx.x * SCAN_B + tid;
    int v = (i < NN) ? g_deg[i] : 0;
    sh[tid] = v;
    __syncthreads();
    for (int off = 1; off < SCAN_B; off <<= 1) {
        int t = (tid >= off) ? sh[tid - off] : 0;
        __syncthreads();
        sh[tid] += t;
        __syncthreads();
    }
    if (i < NN) g_rowptr[i] = sh[tid] - v;           // exclusive partial
    if (tid == SCAN_B - 1) g_bsums[blockIdx.x] = sh[tid];
}

__global__ void scan_sums_k(int nb) {
    __shared__ int sh[64];
    int tid = threadIdx.x;
    int v = (tid < nb) ? g_bsums[tid] : 0;
    sh[tid] = v;
    __syncthreads();
    for (int off = 1; off < 64; off <<= 1) {
        int t = (tid >= off) ? sh[tid - off] : 0;
        __syncthreads();
        sh[tid] += t;
        __syncthreads();
    }
    if (tid < nb) g_bsums[tid] = sh[tid] - v;        // exclusive
}

__global__ void scan_add_k() {
    int i = blockIdx.x * SCAN_B + threadIdx.x;
    if (i < NN) g_rowptr[i] += g_bsums[blockIdx.x];
    if (i == 0) g_rowptr[NN] = EE;
}

__global__ void scatter_k(const int* __restrict__ row, const int* __restrict__ col) {
    int e = blockIdx.x * blockDim.x + threadIdx.x;
    if (e < EE) {
        int r = row[e];
        int p = atomicAdd(&g_cursor[r], 1);
        g_colidx[g_rowptr[r] + p] = col[e];
    }
}

// ---------------------------------------------------------------------------
// Aggregation + tx1 (H=256): one block per node, one thread per channel
//   g_T[i][c] = neg_scale * sum_{j in nbrs(i)} X[j][c] + diag[i] * X[i][c]
// ---------------------------------------------------------------------------
__global__ void agg256_k(const float* __restrict__ X) {
    int i = blockIdx.x;
    int c = threadIdx.x;
    int s = g_rowptr[i];
    int e = g_rowptr[i + 1];
    float sum = 0.0f;
    int k = s;
    for (; k + 4 <= e; k += 4) {
        int j0 = g_colidx[k + 0];
        int j1 = g_colidx[k + 1];
        int j2 = g_colidx[k + 2];
        int j3 = g_colidx[k + 3];
        sum += X[(size_t)j0 * HH + c];
        sum += X[(size_t)j1 * HH + c];
        sum += X[(size_t)j2 * HH + c];
        sum += X[(size_t)j3 * HH + c];
    }
    for (; k < e; k++) sum += X[(size_t)g_colidx[k] * HH + c];
    g_T[(size_t)i * HH + c] = g_negscale * sum + g_diag[i] * X[(size_t)i * HH + c];
}

// Aggregation + tx1 for C=3 (input layer): one thread per node.
__global__ void agg3_k(const float* __restrict__ X) {
    int i = blockIdx.x * blockDim.x + threadIdx.x;
    if (i >= NN) return;
    int s = g_rowptr[i];
    int e = g_rowptr[i + 1];
    float s0 = 0.f, s1 = 0.f, s2 = 0.f;
    for (int k = s; k < e; k++) {
        int j = g_colidx[k];
        s0 += X[j * 3 + 0];
        s1 += X[j * 3 + 1];
        s2 += X[j * 3 + 2];
    }
    float d = g_diag[i], ns = g_negscale;
    g_T3[i * 3 + 0] = ns * s0 + d * X[i * 3 + 0];
    g_T3[i * 3 + 1] = ns * s1 + d * X[i * 3 + 1];
    g_T3[i * 3 + 2] = ns * s2 + d * X[i * 3 + 2];
}

// ---------------------------------------------------------------------------
// Input cheb: Y = relu(x @ Wi0 + tx1_3 @ Wi1 + bi)    (K=3)
// One thread owns one output channel, loops over nodes.
// ---------------------------------------------------------------------------
__global__ void input_gemm_k(const float* __restrict__ X,
                             const float* __restrict__ Wi0,
                             const float* __restrict__ Wi1,
                             const float* __restrict__ bi,
                             float* __restrict__ Y) {
    int c = threadIdx.x;   // 0..255
    float w00 = Wi0[0 * HH + c], w01 = Wi0[1 * HH + c], w02 = Wi0[2 * HH + c];
    float w10 = Wi1[0 * HH + c], w11 = Wi1[1 * HH + c], w12 = Wi1[2 * HH + c];
    float b = bi[c];
    const int npb = (NN + gridDim.x - 1) / gridDim.x;
    int i0 = blockIdx.x * npb;
    int i1 = min(i0 + npb, NN);
    for (int i = i0; i < i1; i++) {
        float x0 = X[i * 3 + 0], x1 = X[i * 3 + 1], x2 = X[i * 3 + 2];
        float t0 = g_T3[i * 3 + 0], t1 = g_T3[i * 3 + 1], t2 = g_T3[i * 3 + 2];
        float v = x0 * w00 + x1 * w01 + x2 * w02
                + t0 * w10 + t1 * w11 + t2 * w12 + b;
        Y[(size_t)i * HH + c] = fmaxf(v, 0.0f);
    }
}

// ---------------------------------------------------------------------------
// Main fused GEMM:  C = epilogue( A1 @ W0 + g_T @ W1 + bias )
//   A1, g_T : [M, 256] row-major    W0, W1 : [256, 256] row-major [k][n]
//   MODE 0: C = relu(acc)
//   MODE 1: C = 0.5f * (R + relu(acc))      (residual average, R == C buffer OK)
// BM=BN=128, BK=16, 8x8 microtiles, 256 threads.
// ---------------------------------------------------------------------------
#define BM 128
#define BN 128
#define BK 16
#define TM 8
#define TN 8

template <int MODE>
__global__ void __launch_bounds__(256, 2)
cheb_gemm_k(const float* __restrict__ A1,
            const float* __restrict__ W0,
            const float* __restrict__ W1,
            const float* __restrict__ bias,
            float* __restrict__ C,
            const float* __restrict__ R,
            int M) {
    __shared__ float As[BK][BM + 4];
    __shared__ float Bs[BK][BN];

    int tid = threadIdx.x;
    int tx = tid & 15;          // 0..15 -> n
    int ty = tid >> 4;          // 0..15 -> m
    int mBase = blockIdx.x * BM;
    int nBase = blockIdx.y * BN;

    float acc[TM][TN];
#pragma unroll
    for (int i = 0; i < TM; i++)
#pragma unroll
        for (int j = 0; j < TN; j++) acc[i][j] = 0.0f;

    int aRow = tid >> 2;            // 0..63 (two passes cover 128 rows)
    int aCol = (tid & 3) * 4;       // 0,4,8,12
    int bRow = tid >> 5;            // 0..7 (two passes cover 16 rows)
    int bCol = (tid & 31) * 4;      // 0..124

    for (int kt = 0; kt < 32; kt++) {
        const float* A = (kt < 16) ? A1 : g_T;
        const float* Wp = (kt < 16) ? W0 : W1;
        int kofs = (kt & 15) * BK;

        // load A tile (transposed into smem)
#pragma unroll
        for (int t = 0; t < 2; t++) {
            int r = aRow + t * 64;
            int gr = mBase + r;
            float4 v = make_float4(0.f, 0.f, 0.f, 0.f);
            if (gr < M) v = *(const float4*)&A[(size_t)gr * HH + kofs + aCol];
            As[aCol + 0][r] = v.x;
            As[aCol + 1][r] = v.y;
            As[aCol + 2][r] = v.z;
            As[aCol + 3][r] = v.w;
        }
        // load B tile
#pragma unroll
        for (int t = 0; t < 2; t++) {
            int kr = bRow + t * 8;
            float4 v = *(const float4*)&Wp[(size_t)(kofs + kr) * HH + nBase + bCol];
            *(float4*)&Bs[kr][bCol] = v;
        }
        __syncthreads();

#pragma unroll
        for (int kk = 0; kk < BK; kk++) {
            float a[TM], b[TN];
#pragma unroll
            for (int i = 0; i < TM; i++) a[i] = As[kk][ty * TM + i];
#pragma unroll
            for (int j = 0; j < TN; j++) b[j] = Bs[kk][tx * TN + j];
#pragma unroll
            for (int i = 0; i < TM; i++)
#pragma unroll
                for (int j = 0; j < TN; j++) acc[i][j] += a[i] * b[j];
        }
        __syncthreads();
    }

    // epilogue
    float bb[TN];
#pragma unroll
    for (int j = 0; j < TN; j++) bb[j] = bias[nBase + tx * TN + j];

#pragma unroll
    for (int i = 0; i < TM; i++) {
        int gr = mBase + ty * TM + i;
        if (gr >= M) continue;
#pragma unroll
        for (int j = 0; j < TN; j++) {
            int gc = nBase + tx * TN + j;
            float v = acc[i][j] + bb[j];
            v = fmaxf(v, 0.0f);
            if (MODE == 1) v = 0.5f * (R[(size_t)gr * HH + gc] + v);
            C[(size_t)gr * HH + gc] = v;
        }
    }
}

// ---------------------------------------------------------------------------
// Final cheb: y2 = Y @ Wf0 + g_T @ Wf1 + bf      (N_out = 3, no relu)
// One warp per node; warp-reduce 3 channels.
// ---------------------------------------------------------------------------
__global__ void final_k(const float* __restrict__ Y,
                        const float* __restrict__ Wf0,
                        const float* __restrict__ Wf1,
                        const float* __restrict__ bf,
                        float* __restrict__ out) {
    int warp = threadIdx.x >> 5;
    int lane = threadIdx.x & 31;
    int node = blockIdx.x * (blockDim.x >> 5) + warp;
    if (node >= NN) return;

    float a0 = 0.f, a1 = 0.f, a2 = 0.f;
    for (int k = lane; k < HH; k += 32) {
        float yv = Y[(size_t)node * HH + k];
        float tv = g_T[(size_t)node * HH + k];
        a0 += yv * Wf0[k * 3 + 0] + tv * Wf1[k * 3 + 0];
        a1 += yv * Wf0[k * 3 + 1] + tv * Wf1[k * 3 + 1];
        a2 += yv * Wf0[k * 3 + 2] + tv * Wf1[k * 3 + 2];
    }
#pragma unroll
    for (int o = 16; o > 0; o >>= 1) {
        a0 += __shfl_xor_sync(0xffffffffu, a0, o);
        a1 += __shfl_xor_sync(0xffffffffu, a1, o);
        a2 += __shfl_xor_sync(0xffffffffu, a2, o);
    }
    if (lane == 0) {
        out[node * 3 + 0] = a0 + bf[0];
        out[node * 3 + 1] = a1 + bf[1];
        out[node * 3 + 2] = a2 + bf[2];
    }
}

// ---------------------------------------------------------------------------
// Launch
// ---------------------------------------------------------------------------
extern "C" void kernel_launch(void* const* d_in, const int* in_sizes, int n_in,
                              void* d_out, int out_size) {
    const float* x   = (const float*)d_in[0];
    const int*   ei  = (const int*)d_in[1];
    const float* Wi0 = (const float*)d_in[2];
    const float* Wi1 = (const float*)d_in[3];
    const float* bi  = (const float*)d_in[4];
    const float* Wr0 = (const float*)d_in[5];
    const float* Wr1 = (const float*)d_in[6];
    const float* br  = (const float*)d_in[7];
    const float* Wf0 = (const float*)d_in[8];
    const float* Wf1 = (const float*)d_in[9];
    const float* bf  = (const float*)d_in[10];

    float* out = (float*)d_out;
    float* Y   = out + (size_t)NN * 3;     // y lives directly in the output buffer

    const int* row = ei;
    const int* col = ei + EE;

    float* dH = nullptr;
    cudaGetSymbolAddress((void**)&dH, g_H);

    const int nTB = (NN + 255) / 256;
    const int eTB = (EE + 255) / 256;
    const int nb  = (NN + SCAN_B - 1) / SCAN_B;   // 49

    // --- graph setup: degree, coefficients, CSR ---
    zero_k<<<nTB, 256>>>();
    degree_k<<<eTB, 256>>>(row);
    maxdeg_k<<<nTB, 256>>>();
    coeff_k<<<nTB, 256>>>();
    scan_block_k<<<nb, SCAN_B>>>();
    scan_sums_k<<<1, 64>>>(nb);
    scan_add_k<<<nb, SCAN_B>>>();
    scatter_k<<<eTB, 256>>>(row, col);

    // --- input layer ---
    agg3_k<<<nTB, 256>>>(x);
    input_gemm_k<<<400, 256>>>(x, Wi0, Wi1, bi, Y);

    // --- residual blocks ---
    dim3 gg((NN + BM - 1) / BM, HH / BN);
    for (int i = 0; i < 3; i++) {
        const float* W0a = Wr0 + (size_t)(2 * i) * HH * HH;
        const float* W1a = Wr1 + (size_t)(2 * i) * HH * HH;
        const float* ba  = br  + (size_t)(2 * i) * HH;
        const float* W0b = Wr0 + (size_t)(2 * i + 1) * HH * HH;
        const float* W1b = Wr1 + (size_t)(2 * i + 1) * HH * HH;
        const float* bb  = br  + (size_t)(2 * i + 1) * HH;

        agg256_k<<<NN, 256>>>(Y);
        cheb_gemm_k<0><<<gg, 256>>>(Y, W0a, W1a, ba, dH, nullptr, NN);
        agg256_k<<<NN, 256>>>(dH);
        cheb_gemm_k<1><<<gg, 256>>>(dH, W0b, W1b, bb, Y, Y, NN);
    }

    // --- final layer ---
    agg256_k<<<NN, 256>>>(Y);
    final_k<<<(NN + 3) / 4, 128>>>(Y, Wf0, Wf1, bf, out);
}

// round 4
// speedup vs baseline: 1.5964x; 1.5964x over previous
#include <cuda_runtime.h>
#include <cuda_bf16.h>
#include <cstdint>

// Problem constants (fixed by the dataset).
#define NN 50000
#define EE 800000
#define HH 256

// ---------------------------------------------------------------------------
// Device scratch (static allocation; no cudaMalloc allowed)
// ---------------------------------------------------------------------------
__device__ int   g_deg[NN];
__device__ int   g_cursor[NN];
__device__ int   g_rowptr[NN + 1];
__device__ int   g_colidx[EE];
__device__ int   g_bsums[64];
__device__ int   g_maxdeg;
__device__ float g_diag[NN];
__device__ float g_negscale;
__device__ float g_T[(size_t)NN * HH];          // tx1 scratch (H channels)
__device__ float g_H[(size_t)NN * HH];          // hidden scratch
__device__ float g_T3[(size_t)NN * 3];          // tx1 scratch (3 channels)

static __device__ __forceinline__ uint32_t cvt_tf32(float f) {
    uint32_t r;
    asm("cvt.rna.tf32.f32 %0, %1;" : "=r"(r) : "f"(f));
    return r;
}

static __device__ __forceinline__ void mma_tf32(float* d,
                                                const uint32_t* a,
                                                const uint32_t* b) {
    asm volatile("mma.sync.aligned.m16n8k8.row.col.f32.tf32.tf32.f32 "
                 "{%0,%1,%2,%3}, {%4,%5,%6,%7}, {%8,%9}, {%0,%1,%2,%3};"
                 : "+f"(d[0]), "+f"(d[1]), "+f"(d[2]), "+f"(d[3])
                 : "r"(a[0]), "r"(a[1]), "r"(a[2]), "r"(a[3]),
                   "r"(b[0]), "r"(b[1]));
}

// ---------------------------------------------------------------------------
// Setup kernels: degree, lambda_max, coefficients, CSR build
// ---------------------------------------------------------------------------
__global__ void zero_k() {
    int i = blockIdx.x * blockDim.x + threadIdx.x;
    if (i < NN) { g_deg[i] = 0; g_cursor[i] = 0; }
    if (i == 0) g_maxdeg = 0;
}

__global__ void degree_k(const int* __restrict__ row) {
    int e = blockIdx.x * blockDim.x + threadIdx.x;
    if (e < EE) atomicAdd(&g_deg[row[e]], 1);
}

__global__ void maxdeg_k() {
    int i = blockIdx.x * blockDim.x + threadIdx.x;
    if (i < NN) atomicMax(&g_maxdeg, g_deg[i]);
}

__global__ void coeff_k() {
    int i = blockIdx.x * blockDim.x + threadIdx.x;
    if (i < NN) {
        float md    = (float)g_maxdeg;
        float lam   = 2.0f * md;
        float scale = 2.0f / lam;
        g_diag[i]   = scale * (float)g_deg[i] - 1.0f;
        if (i == 0) g_negscale = -scale;
    }
}

#define SCAN_B 1024
__global__ void scan_block_k() {
    __shared__ int sh[SCAN_B];
    int tid = threadIdx.x;
    int i = blockIdx.x * SCAN_B + tid;
    int v = (i < NN) ? g_deg[i] : 0;
    sh[tid] = v;
    __syncthreads();
    for (int off = 1; off < SCAN_B; off <<= 1) {
        int t = (tid >= off) ? sh[tid - off] : 0;
        __syncthreads();
        sh[tid] += t;
        __syncthreads();
    }
    if (i < NN) g_rowptr[i] = sh[tid] - v;
    if (tid == SCAN_B - 1) g_bsums[blockIdx.x] = sh[tid];
}

__global__ void scan_sums_k(int nb) {
    __shared__ int sh[64];
    int tid = threadIdx.x;
    int v = (tid < nb) ? g_bsums[tid] : 0;
    sh[tid] = v;
    __syncthreads();
    for (int off = 1; off < 64; off <<= 1) {
        int t = (tid >= off) ? sh[tid - off] : 0;
        __syncthreads();
        sh[tid] += t;
        __syncthreads();
    }
    if (tid < nb) g_bsums[tid] = sh[tid] - v;
}

__global__ void scan_add_k() {
    int i = blockIdx.x * SCAN_B + threadIdx.x;
    if (i < NN) g_rowptr[i] += g_bsums[blockIdx.x];
    if (i == 0) g_rowptr[NN] = EE;
}

__global__ void scatter_k(const int* __restrict__ row, const int* __restrict__ col) {
    int e = blockIdx.x * blockDim.x + threadIdx.x;
    if (e < EE) {
        int r = row[e];
        int p = atomicAdd(&g_cursor[r], 1);
        g_colidx[g_rowptr[r] + p] = col[e];
    }
}

// ---------------------------------------------------------------------------
// Aggregation + tx1 (H=256): one block per node, one thread per channel
// ---------------------------------------------------------------------------
__global__ void agg256_k(const float* __restrict__ X) {
    int i = blockIdx.x;
    int c = threadIdx.x;
    int s = g_rowptr[i];
    int e = g_rowptr[i + 1];
    float sum = 0.0f;
    int k = s;
    for (; k + 4 <= e; k += 4) {
        int j0 = g_colidx[k + 0];
        int j1 = g_colidx[k + 1];
        int j2 = g_colidx[k + 2];
        int j3 = g_colidx[k + 3];
        sum += X[(size_t)j0 * HH + c];
        sum += X[(size_t)j1 * HH + c];
        sum += X[(size_t)j2 * HH + c];
        sum += X[(size_t)j3 * HH + c];
    }
    for (; k < e; k++) sum += X[(size_t)g_colidx[k] * HH + c];
    g_T[(size_t)i * HH + c] = g_negscale * sum + g_diag[i] * X[(size_t)i * HH + c];
}

__global__ void agg3_k(const float* __restrict__ X) {
    int i = blockIdx.x * blockDim.x + threadIdx.x;
    if (i >= NN) return;
    int s = g_rowptr[i];
    int e = g_rowptr[i + 1];
    float s0 = 0.f, s1 = 0.f, s2 = 0.f;
    for (int k = s; k < e; k++) {
        int j = g_colidx[k];
        s0 += X[j * 3 + 0];
        s1 += X[j * 3 + 1];
        s2 += X[j * 3 + 2];
    }
    float d = g_diag[i], ns = g_negscale;
    g_T3[i * 3 + 0] = ns * s0 + d * X[i * 3 + 0];
    g_T3[i * 3 + 1] = ns * s1 + d * X[i * 3 + 1];
    g_T3[i * 3 + 2] = ns * s2 + d * X[i * 3 + 2];
}

// ---------------------------------------------------------------------------
// Input cheb: Y = relu(x @ Wi0 + tx1_3 @ Wi1 + bi)
// ---------------------------------------------------------------------------
__global__ void input_gemm_k(const float* __restrict__ X,
                             const float* __restrict__ Wi0,
                             const float* __restrict__ Wi1,
                             const float* __restrict__ bi,
                             float* __restrict__ Y) {
    int c = threadIdx.x;
    float w00 = Wi0[0 * HH + c], w01 = Wi0[1 * HH + c], w02 = Wi0[2 * HH + c];
    float w10 = Wi1[0 * HH + c], w11 = Wi1[1 * HH + c], w12 = Wi1[2 * HH + c];
    float b = bi[c];
    const int npb = (NN + gridDim.x - 1) / gridDim.x;
    int i0 = blockIdx.x * npb;
    int i1 = min(i0 + npb, NN);
    for (int i = i0; i < i1; i++) {
        float x0 = X[i * 3 + 0], x1 = X[i * 3 + 1], x2 = X[i * 3 + 2];
        float t0 = g_T3[i * 3 + 0], t1 = g_T3[i * 3 + 1], t2 = g_T3[i * 3 + 2];
        float v = x0 * w00 + x1 * w01 + x2 * w02
                + t0 * w10 + t1 * w11 + t2 * w12 + b;
        Y[(size_t)i * HH + c] = fmaxf(v, 0.0f);
    }
}

// ---------------------------------------------------------------------------
// tf32 mma.sync GEMM: C = epilogue( A1 @ W0 + g_T @ W1 + bias )
//   A1, g_T : [NN, 256] fp32 row-major (K halves 0-255 / 256-511)
//   W0, W1  : [256 k, 256 n] fp32 row-major
//   MODE 0: C = relu(acc + bias)
//   MODE 1: C = 0.5 * (R + relu(acc + bias))   (R == C aliasing OK)
// Tile: BM=128, BN=128, BK=32, double-buffered SMEM, 256 threads (8 warps).
// Warp tile 64x32, built from m16n8k8 tf32 mma.sync.
// Inputs rounded to tf32 with cvt.rna at SMEM-store time (truncation would
// bias the result by ~-2e-3 over 8 layers and fail the 1e-3 gate).
// ---------------------------------------------------------------------------
#define A_STRIDE 36    // floats per A row (32 + 4 pad); 144B, 16B-aligned
#define B_STRIDE 136   // floats per B row (128 + 8 pad); 544B, 16B-aligned
#define A_TILE   (128 * A_STRIDE)   // 4608 floats
#define B_TILE   (32 * B_STRIDE)    // 4352 floats
#define GEMM_SMEM ((2 * A_TILE + 2 * B_TILE) * 4)   // 71680 B

template <int MODE>
__global__ void __launch_bounds__(256)
gemm_mma_k(const float* __restrict__ A1,
           const float* __restrict__ W0,
           const float* __restrict__ W1,
           const float* __restrict__ bias,
           float* __restrict__ C,
           const float* __restrict__ R) {
    extern __shared__ float smem[];
    float* As[2] = { smem, smem + A_TILE };
    float* Bs[2] = { smem + 2 * A_TILE, smem + 2 * A_TILE + B_TILE };

    const int tid    = threadIdx.x;
    const int lane   = tid & 31;
    const int wid    = tid >> 5;
    const int warp_m = wid >> 2;          // 0..1 -> 64-row slab
    const int warp_n = wid & 3;           // 0..3 -> 32-col slab
    const int g      = lane >> 2;         // 0..7
    const int cc     = lane & 3;          // 0..3
    const int mBase  = blockIdx.x * 128;
    const int nBase  = blockIdx.y * 128;

    float acc[4][4][4];
#pragma unroll
    for (int mt = 0; mt < 4; mt++)
#pragma unroll
        for (int nt = 0; nt < 4; nt++)
#pragma unroll
            for (int q = 0; q < 4; q++) acc[mt][nt][q] = 0.0f;

    // ---- stage chunk c (32 wide in K) into buffer s ----
    auto load_chunk = [&](int c, int s) {
        const float* asrc = (c < 8) ? A1 : (const float*)g_T;
        const float* wsrc = (c < 8) ? W0 : W1;
        const int kel = (c & 7) * 32;
        float* at = As[s];
        float* bt = Bs[s];
        // A: 128 rows x 32 k  (1024 float4, 4 per thread)
#pragma unroll
        for (int p = 0; p < 4; p++) {
            int idx  = tid + p * 256;
            int r    = idx >> 3;
            int col4 = (idx & 7) * 4;
            int gr   = mBase + r;
            float4 v = make_float4(0.f, 0.f, 0.f, 0.f);
            if (gr < NN) v = *(const float4*)&asrc[(size_t)gr * 256 + kel + col4];
            uint4 u = { cvt_tf32(v.x), cvt_tf32(v.y), cvt_tf32(v.z), cvt_tf32(v.w) };
            *(uint4*)&at[r * A_STRIDE + col4] = u;
        }
        // B: 32 k-rows x 128 n  (1024 float4, 4 per thread)
#pragma unroll
        for (int p = 0; p < 4; p++) {
            int idx  = tid + p * 256;
            int kr   = idx >> 5;
            int col4 = (idx & 31) * 4;
            float4 v = *(const float4*)&wsrc[(size_t)(kel + kr) * 256 + nBase + col4];
            uint4 u = { cvt_tf32(v.x), cvt_tf32(v.y), cvt_tf32(v.z), cvt_tf32(v.w) };
            *(uint4*)&bt[kr * B_STRIDE + col4] = u;
        }
    };

    load_chunk(0, 0);
    __syncthreads();

    for (int c = 0; c < 16; c++) {
        int s = c & 1;
        if (c < 15) load_chunk(c + 1, s ^ 1);

        const float* at = As[s];
        const float* bt = Bs[s];
#pragma unroll
        for (int ks = 0; ks < 4; ks++) {
            const int ko = ks * 8;
            uint32_t a[4][4];
#pragma unroll
            for (int mt = 0; mt < 4; mt++) {
                int r0 = warp_m * 64 + mt * 16;
                a[mt][0] = __float_as_uint(at[(r0 + g)     * A_STRIDE + ko + cc]);
                a[mt][1] = __float_as_uint(at[(r0 + g + 8) * A_STRIDE + ko + cc]);
                a[mt][2] = __float_as_uint(at[(r0 + g)     * A_STRIDE + ko + cc + 4]);
                a[mt][3] = __float_as_uint(at[(r0 + g + 8) * A_STRIDE + ko + cc + 4]);
            }
            uint32_t b[4][2];
#pragma unroll
            for (int nt = 0; nt < 4; nt++) {
                int n0 = warp_n * 32 + nt * 8 + g;
                b[nt][0] = __float_as_uint(bt[(ko + cc)     * B_STRIDE + n0]);
                b[nt][1] = __float_as_uint(bt[(ko + cc + 4) * B_STRIDE + n0]);
            }
#pragma unroll
            for (int mt = 0; mt < 4; mt++)
#pragma unroll
                for (int nt = 0; nt < 4; nt++)
                    mma_tf32(acc[mt][nt], a[mt], b[nt]);
        }
        __syncthreads();
    }

    // ---- epilogue: bias + relu (+ residual average) ----
#pragma unroll
    for (int mt = 0; mt < 4; mt++) {
        int r0 = mBase + warp_m * 64 + mt * 16 + g;
#pragma unroll
        for (int nt = 0; nt < 4; nt++) {
            int n0 = nBase + warp_n * 32 + nt * 8 + 2 * cc;
            float2 bv = *(const float2*)&bias[n0];
            if (r0 < NN) {
                float2 o;
                o.x = fmaxf(acc[mt][nt][0] + bv.x, 0.f);
                o.y = fmaxf(acc[mt][nt][1] + bv.y, 0.f);
                if (MODE == 1) {
                    float2 rr = *(const float2*)&R[(size_t)r0 * 256 + n0];
                    o.x = 0.5f * (o.x + rr.x);
                    o.y = 0.5f * (o.y + rr.y);
                }
                *(float2*)&C[(size_t)r0 * 256 + n0] = o;
            }
            int r1 = r0 + 8;
            if (r1 < NN) {
                float2 o;
                o.x = fmaxf(acc[mt][nt][2] + bv.x, 0.f);
                o.y = fmaxf(acc[mt][nt][3] + bv.y, 0.f);
                if (MODE == 1) {
                    float2 rr = *(const float2*)&R[(size_t)r1 * 256 + n0];
                    o.x = 0.5f * (o.x + rr.x);
                    o.y = 0.5f * (o.y + rr.y);
                }
                *(float2*)&C[(size_t)r1 * 256 + n0] = o;
            }
        }
    }
}

// ---------------------------------------------------------------------------
// Final cheb: y2 = Y @ Wf0 + g_T @ Wf1 + bf
// ---------------------------------------------------------------------------
__global__ void final_k(const float* __restrict__ Y,
                        const float* __restrict__ Wf0,
                        const float* __restrict__ Wf1,
                        const float* __restrict__ bf,
                        float* __restrict__ out) {
    int warp = threadIdx.x >> 5;
    int lane = threadIdx.x & 31;
    int node = blockIdx.x * (blockDim.x >> 5) + warp;
    if (node >= NN) return;

    float a0 = 0.f, a1 = 0.f, a2 = 0.f;
    for (int k = lane; k < HH; k += 32) {
        float yv = Y[(size_t)node * HH + k];
        float tv = g_T[(size_t)node * HH + k];
        a0 += yv * Wf0[k * 3 + 0] + tv * Wf1[k * 3 + 0];
        a1 += yv * Wf0[k * 3 + 1] + tv * Wf1[k * 3 + 1];
        a2 += yv * Wf0[k * 3 + 2] + tv * Wf1[k * 3 + 2];
    }
#pragma unroll
    for (int o = 16; o > 0; o >>= 1) {
        a0 += __shfl_xor_sync(0xffffffffu, a0, o);
        a1 += __shfl_xor_sync(0xffffffffu, a1, o);
        a2 += __shfl_xor_sync(0xffffffffu, a2, o);
    }
    if (lane == 0) {
        out[node * 3 + 0] = a0 + bf[0];
        out[node * 3 + 1] = a1 + bf[1];
        out[node * 3 + 2] = a2 + bf[2];
    }
}

// ---------------------------------------------------------------------------
// Launch
// ---------------------------------------------------------------------------
extern "C" void kernel_launch(void* const* d_in, const int* in_sizes, int n_in,
                              void* d_out, int out_size) {
    const float* x   = (const float*)d_in[0];
    const int*   ei  = (const int*)d_in[1];
    const float* Wi0 = (const float*)d_in[2];
    const float* Wi1 = (const float*)d_in[3];
    const float* bi  = (const float*)d_in[4];
    const float* Wr0 = (const float*)d_in[5];
    const float* Wr1 = (const float*)d_in[6];
    const float* br  = (const float*)d_in[7];
    const float* Wf0 = (const float*)d_in[8];
    const float* Wf1 = (const float*)d_in[9];
    const float* bf  = (const float*)d_in[10];

    float* out = (float*)d_out;
    float* Y   = out + (size_t)NN * 3;

    const int* row = ei;
    const int* col = ei + EE;

    float* dH = nullptr;
    cudaGetSymbolAddress((void**)&dH, g_H);

    cudaFuncSetAttribute(gemm_mma_k<0>, cudaFuncAttributeMaxDynamicSharedMemorySize, GEMM_SMEM);
    cudaFuncSetAttribute(gemm_mma_k<1>, cudaFuncAttributeMaxDynamicSharedMemorySize, GEMM_SMEM);

    const int nTB = (NN + 255) / 256;
    const int eTB = (EE + 255) / 256;
    const int nb  = (NN + SCAN_B - 1) / SCAN_B;

    // --- graph setup: degree, coefficients, CSR ---
    zero_k<<<nTB, 256>>>();
    degree_k<<<eTB, 256>>>(row);
    maxdeg_k<<<nTB, 256>>>();
    coeff_k<<<nTB, 256>>>();
    scan_block_k<<<nb, SCAN_B>>>();
    scan_sums_k<<<1, 64>>>(nb);
    scan_add_k<<<nb, SCAN_B>>>();
    scatter_k<<<eTB, 256>>>(row, col);

    // --- input layer ---
    agg3_k<<<nTB, 256>>>(x);
    input_gemm_k<<<400, 256>>>(x, Wi0, Wi1, bi, Y);

    // --- residual blocks (tf32 mma.sync GEMMs) ---
    dim3 gg((NN + 127) / 128, 2);
    for (int i = 0; i < 3; i++) {
        const float* W0a = Wr0 + (size_t)(2 * i) * HH * HH;
        const float* W1a = Wr1 + (size_t)(2 * i) * HH * HH;
        const float* ba  = br  + (size_t)(2 * i) * HH;
        const float* W0b = Wr0 + (size_t)(2 * i + 1) * HH * HH;
        const float* W1b = Wr1 + (size_t)(2 * i + 1) * HH * HH;
        const float* bb  = br  + (size_t)(2 * i + 1) * HH;

        agg256_k<<<NN, 256>>>(Y);
        gemm_mma_k<0><<<gg, 256, GEMM_SMEM>>>(Y, W0a, W1a, ba, dH, nullptr);
        agg256_k<<<NN, 256>>>(dH);
        gemm_mma_k<1><<<gg, 256, GEMM_SMEM>>>(dH, W0b, W1b, bb, Y, Y);
    }

    // --- final layer ---
    agg256_k<<<NN, 256>>>(Y);
    final_k<<<(NN + 3) / 4, 128>>>(Y, Wf0, Wf1, bf, out);
}

// round 5
// speedup vs baseline: 1.7120x; 1.0724x over previous
#include <cuda_runtime.h>
#include <cuda_bf16.h>
#include <cstdint>

// Problem constants (fixed by the dataset).
#define NN 50000
#define EE 800000
#define HH 256

// ---------------------------------------------------------------------------
// Device scratch (static allocation; no cudaMalloc allowed)
// ---------------------------------------------------------------------------
__device__ int   g_deg[NN];
__device__ int   g_cursor[NN];
__device__ int   g_rowptr[NN + 1];
__device__ int   g_colidx[EE];
__device__ int   g_bsums[64];
__device__ int   g_maxdeg;
__device__ float g_diag[NN];
__device__ float g_negscale;
__device__ float g_T[(size_t)NN * HH];          // tx1 scratch (H channels)
__device__ float g_H[(size_t)NN * HH];          // hidden scratch
__device__ float g_T3[(size_t)NN * 3];          // tx1 scratch (3 channels)

static __device__ __forceinline__ uint32_t cvt_tf32(float f) {
    uint32_t r;
    asm("cvt.rna.tf32.f32 %0, %1;" : "=r"(r) : "f"(f));
    return r;
}

static __device__ __forceinline__ void mma_tf32(float* d,
                                                const uint32_t* a,
                                                const uint32_t* b) {
    asm volatile("mma.sync.aligned.m16n8k8.row.col.f32.tf32.tf32.f32 "
                 "{%0,%1,%2,%3}, {%4,%5,%6,%7}, {%8,%9}, {%0,%1,%2,%3};"
                 : "+f"(d[0]), "+f"(d[1]), "+f"(d[2]), "+f"(d[3])
                 : "r"(a[0]), "r"(a[1]), "r"(a[2]), "r"(a[3]),
                   "r"(b[0]), "r"(b[1]));
}

// ---------------------------------------------------------------------------
// Setup kernels: degree, lambda_max, coefficients, CSR build
// ---------------------------------------------------------------------------
__global__ void zero_k() {
    int i = blockIdx.x * blockDim.x + threadIdx.x;
    if (i < NN) { g_deg[i] = 0; g_cursor[i] = 0; }
    if (i == 0) g_maxdeg = 0;
}

__global__ void degree_k(const int* __restrict__ row) {
    int e = blockIdx.x * blockDim.x + threadIdx.x;
    if (e < EE) atomicAdd(&g_deg[row[e]], 1);
}

__global__ void maxdeg_k() {
    int i = blockIdx.x * blockDim.x + threadIdx.x;
    if (i < NN) atomicMax(&g_maxdeg, g_deg[i]);
}

__global__ void coeff_k() {
    int i = blockIdx.x * blockDim.x + threadIdx.x;
    if (i < NN) {
        float md    = (float)g_maxdeg;
        float lam   = 2.0f * md;
        float scale = 2.0f / lam;
        g_diag[i]   = scale * (float)g_deg[i] - 1.0f;
        if (i == 0) g_negscale = -scale;
    }
}

#define SCAN_B 1024
__global__ void scan_block_k() {
    __shared__ int sh[SCAN_B];
    int tid = threadIdx.x;
    int i = blockIdx.x * SCAN_B + tid;
    int v = (i < NN) ? g_deg[i] : 0;
    sh[tid] = v;
    __syncthreads();
    for (int off = 1; off < SCAN_B; off <<= 1) {
        int t = (tid >= off) ? sh[tid - off] : 0;
        __syncthreads();
        sh[tid] += t;
        __syncthreads();
    }
    if (i < NN) g_rowptr[i] = sh[tid] - v;
    if (tid == SCAN_B - 1) g_bsums[blockIdx.x] = sh[tid];
}

__global__ void scan_sums_k(int nb) {
    __shared__ int sh[64];
    int tid = threadIdx.x;
    int v = (tid < nb) ? g_bsums[tid] : 0;
    sh[tid] = v;
    __syncthreads();
    for (int off = 1; off < 64; off <<= 1) {
        int t = (tid >= off) ? sh[tid - off] : 0;
        __syncthreads();
        sh[tid] += t;
        __syncthreads();
    }
    if (tid < nb) g_bsums[tid] = sh[tid] - v;
}

__global__ void scan_add_k() {
    int i = blockIdx.x * SCAN_B + threadIdx.x;
    if (i < NN) g_rowptr[i] += g_bsums[blockIdx.x];
    if (i == 0) g_rowptr[NN] = EE;
}

__global__ void scatter_k(const int* __restrict__ row, const int* __restrict__ col) {
    int e = blockIdx.x * blockDim.x + threadIdx.x;
    if (e < EE) {
        int r = row[e];
        int p = atomicAdd(&g_cursor[r], 1);
        g_colidx[g_rowptr[r] + p] = col[e];
    }
}

// ---------------------------------------------------------------------------
// Aggregation + tx1 (H=256): one block per node, one thread per channel
// ---------------------------------------------------------------------------
__global__ void agg256_k(const float* __restrict__ X) {
    int i = blockIdx.x;
    int c = threadIdx.x;
    int s = g_rowptr[i];
    int e = g_rowptr[i + 1];
    float sum = 0.0f;
    int k = s;
    for (; k + 8 <= e; k += 8) {
        int j0 = g_colidx[k + 0];
        int j1 = g_colidx[k + 1];
        int j2 = g_colidx[k + 2];
        int j3 = g_colidx[k + 3];
        int j4 = g_colidx[k + 4];
        int j5 = g_colidx[k + 5];
        int j6 = g_colidx[k + 6];
        int j7 = g_colidx[k + 7];
        float v0 = __ldg(&X[(size_t)j0 * HH + c]);
        float v1 = __ldg(&X[(size_t)j1 * HH + c]);
        float v2 = __ldg(&X[(size_t)j2 * HH + c]);
        float v3 = __ldg(&X[(size_t)j3 * HH + c]);
        float v4 = __ldg(&X[(size_t)j4 * HH + c]);
        float v5 = __ldg(&X[(size_t)j5 * HH + c]);
        float v6 = __ldg(&X[(size_t)j6 * HH + c]);
        float v7 = __ldg(&X[(size_t)j7 * HH + c]);
        sum += ((v0 + v1) + (v2 + v3)) + ((v4 + v5) + (v6 + v7));
    }
    for (; k < e; k++) sum += __ldg(&X[(size_t)g_colidx[k] * HH + c]);
    g_T[(size_t)i * HH + c] = g_negscale * sum + g_diag[i] * X[(size_t)i * HH + c];
}

__global__ void agg3_k(const float* __restrict__ X) {
    int i = blockIdx.x * blockDim.x + threadIdx.x;
    if (i >= NN) return;
    int s = g_rowptr[i];
    int e = g_rowptr[i + 1];
    float s0 = 0.f, s1 = 0.f, s2 = 0.f;
    for (int k = s; k < e; k++) {
        int j = g_colidx[k];
        s0 += X[j * 3 + 0];
        s1 += X[j * 3 + 1];
        s2 += X[j * 3 + 2];
    }
    float d = g_diag[i], ns = g_negscale;
    g_T3[i * 3 + 0] = ns * s0 + d * X[i * 3 + 0];
    g_T3[i * 3 + 1] = ns * s1 + d * X[i * 3 + 1];
    g_T3[i * 3 + 2] = ns * s2 + d * X[i * 3 + 2];
}

// ---------------------------------------------------------------------------
// Input cheb: Y = relu(x @ Wi0 + tx1_3 @ Wi1 + bi)
// ---------------------------------------------------------------------------
__global__ void input_gemm_k(const float* __restrict__ X,
                             const float* __restrict__ Wi0,
                             const float* __restrict__ Wi1,
                             const float* __restrict__ bi,
                             float* __restrict__ Y) {
    int c = threadIdx.x;
    float w00 = Wi0[0 * HH + c], w01 = Wi0[1 * HH + c], w02 = Wi0[2 * HH + c];
    float w10 = Wi1[0 * HH + c], w11 = Wi1[1 * HH + c], w12 = Wi1[2 * HH + c];
    float b = bi[c];
    const int npb = (NN + gridDim.x - 1) / gridDim.x;
    int i0 = blockIdx.x * npb;
    int i1 = min(i0 + npb, NN);
    for (int i = i0; i < i1; i++) {
        float x0 = X[i * 3 + 0], x1 = X[i * 3 + 1], x2 = X[i * 3 + 2];
        float t0 = g_T3[i * 3 + 0], t1 = g_T3[i * 3 + 1], t2 = g_T3[i * 3 + 2];
        float v = x0 * w00 + x1 * w01 + x2 * w02
                + t0 * w10 + t1 * w11 + t2 * w12 + b;
        Y[(size_t)i * HH + c] = fmaxf(v, 0.0f);
    }
}

// ---------------------------------------------------------------------------
// tf32 mma.sync GEMM: C = epilogue( A1 @ W0 + g_T @ W1 + bias )
// Pipelined: LDG chunk c+1 into registers -> MMA chunk c -> cvt+STS -> sync.
// Tile: BM=128, BN=128, BK=32, double-buffered SMEM, 256 threads (8 warps).
// Both SMEM layouts are bank-conflict-free for the fragment access patterns
// (A banks 4g+cc, B banks 8cc+g -> 32 distinct).
// ---------------------------------------------------------------------------
#define A_STRIDE 36    // floats per A row (32 + 4 pad); 144B, 16B-aligned
#define B_STRIDE 136   // floats per B row (128 + 8 pad); 544B, 16B-aligned
#define A_TILE   (128 * A_STRIDE)   // 4608 floats
#define B_TILE   (32 * B_STRIDE)    // 4352 floats
#define GEMM_SMEM ((2 * A_TILE + 2 * B_TILE) * 4)   // 71680 B

template <int MODE>
__global__ void __launch_bounds__(256)
gemm_mma_k(const float* __restrict__ A1,
           const float* __restrict__ W0,
           const float* __restrict__ W1,
           const float* __restrict__ bias,
           float* __restrict__ C,
           const float* __restrict__ R) {
    extern __shared__ float smem[];
    float* As[2] = { smem, smem + A_TILE };
    float* Bs[2] = { smem + 2 * A_TILE, smem + 2 * A_TILE + B_TILE };

    const int tid    = threadIdx.x;
    const int lane   = tid & 31;
    const int wid    = tid >> 5;
    const int warp_m = wid >> 2;          // 0..1 -> 64-row slab
    const int warp_n = wid & 3;           // 0..3 -> 32-col slab
    const int g      = lane >> 2;         // 0..7
    const int cc     = lane & 3;          // 0..3
    const int mBase  = blockIdx.x * 128;
    const int nBase  = blockIdx.y * 128;

    float acc[4][4][4];
#pragma unroll
    for (int mt = 0; mt < 4; mt++)
#pragma unroll
        for (int nt = 0; nt < 4; nt++)
#pragma unroll
            for (int q = 0; q < 4; q++) acc[mt][nt][q] = 0.0f;

    // precomputed per-thread load coordinates
    const int aR    = tid >> 3;            // A row within tile (p adds 32)
    const int aCol4 = (tid & 7) * 4;       // A k offset
    const int bK    = tid >> 5;            // B k row (p adds 8)
    const int bCol4 = (tid & 31) * 4;      // B n offset

    float4 stA[4], stB[4];

    // Issue global loads for chunk c into registers (no SMEM writes yet).
    auto ldg_chunk = [&](int c) {
        const float* asrc = (c < 8) ? A1 : (const float*)g_T;
        const float* wsrc = (c < 8) ? W0 : W1;
        const int kel = (c & 7) * 32;
#pragma unroll
        for (int p = 0; p < 4; p++) {
            int r  = aR + p * 32;
            int gr = mBase + r;
            stA[p] = make_float4(0.f, 0.f, 0.f, 0.f);
            if (gr < NN) stA[p] = *(const float4*)&asrc[(size_t)gr * 256 + kel + aCol4];
        }
#pragma unroll
        for (int p = 0; p < 4; p++) {
            int kr = bK + p * 8;
            stB[p] = *(const float4*)&wsrc[(size_t)(kel + kr) * 256 + nBase + bCol4];
        }
    };

    // Round to tf32 and store staged registers into buffer s.
    auto sts_chunk = [&](int s) {
        float* at = As[s];
        float* bt = Bs[s];
#pragma unroll
        for (int p = 0; p < 4; p++) {
            int r = aR + p * 32;
            uint4 u = { cvt_tf32(stA[p].x), cvt_tf32(stA[p].y),
                        cvt_tf32(stA[p].z), cvt_tf32(stA[p].w) };
            *(uint4*)&at[r * A_STRIDE + aCol4] = u;
        }
#pragma unroll
        for (int p = 0; p < 4; p++) {
            int kr = bK + p * 8;
            uint4 u = { cvt_tf32(stB[p].x), cvt_tf32(stB[p].y),
                        cvt_tf32(stB[p].z), cvt_tf32(stB[p].w) };
            *(uint4*)&bt[kr * B_STRIDE + bCol4] = u;
        }
    };

    ldg_chunk(0);
    sts_chunk(0);
    __syncthreads();

    for (int c = 0; c < 16; c++) {
        int s = c & 1;
        if (c < 15) ldg_chunk(c + 1);   // LDGs in flight during the MMA loop

        const float* at = As[s];
        const float* bt = Bs[s];
#pragma unroll
        for (int ks = 0; ks < 4; ks++) {
            const int ko = ks * 8;
            uint32_t a[4][4];
#pragma unroll
            for (int mt = 0; mt < 4; mt++) {
                int r0 = warp_m * 64 + mt * 16;
                a[mt][0] = __float_as_uint(at[(r0 + g)     * A_STRIDE + ko + cc]);
                a[mt][1] = __float_as_uint(at[(r0 + g + 8) * A_STRIDE + ko + cc]);
                a[mt][2] = __float_as_uint(at[(r0 + g)     * A_STRIDE + ko + cc + 4]);
                a[mt][3] = __float_as_uint(at[(r0 + g + 8) * A_STRIDE + ko + cc + 4]);
            }
            uint32_t b[4][2];
#pragma unroll
            for (int nt = 0; nt < 4; nt++) {
                int n0 = warp_n * 32 + nt * 8 + g;
                b[nt][0] = __float_as_uint(bt[(ko + cc)     * B_STRIDE + n0]);
                b[nt][1] = __float_as_uint(bt[(ko + cc + 4) * B_STRIDE + n0]);
            }
#pragma unroll
            for (int mt = 0; mt < 4; mt++)
#pragma unroll
                for (int nt = 0; nt < 4; nt++)
                    mma_tf32(acc[mt][nt], a[mt], b[nt]);
        }

        if (c < 15) sts_chunk(s ^ 1);   // safe: s^1 reads finished at prev sync
        __syncthreads();
    }

    // ---- epilogue: bias + relu (+ residual average) ----
#pragma unroll
    for (int mt = 0; mt < 4; mt++) {
        int r0 = mBase + warp_m * 64 + mt * 16 + g;
#pragma unroll
        for (int nt = 0; nt < 4; nt++) {
            int n0 = nBase + warp_n * 32 + nt * 8 + 2 * cc;
            float2 bv = *(const float2*)&bias[n0];
            if (r0 < NN) {
                float2 o;
                o.x = fmaxf(acc[mt][nt][0] + bv.x, 0.f);
                o.y = fmaxf(acc[mt][nt][1] + bv.y, 0.f);
                if (MODE == 1) {
                    float2 rr = *(const float2*)&R[(size_t)r0 * 256 + n0];
                    o.x = 0.5f * (o.x + rr.x);
                    o.y = 0.5f * (o.y + rr.y);
                }
                *(float2*)&C[(size_t)r0 * 256 + n0] = o;
            }
            int r1 = r0 + 8;
            if (r1 < NN) {
                float2 o;
                o.x = fmaxf(acc[mt][nt][2] + bv.x, 0.f);
                o.y = fmaxf(acc[mt][nt][3] + bv.y, 0.f);
                if (MODE == 1) {
                    float2 rr = *(const float2*)&R[(size_t)r1 * 256 + n0];
                    o.x = 0.5f * (o.x + rr.x);
                    o.y = 0.5f * (o.y + rr.y);
                }
                *(float2*)&C[(size_t)r1 * 256 + n0] = o;
            }
        }
    }
}

// ---------------------------------------------------------------------------
// Final cheb: y2 = Y @ Wf0 + g_T @ Wf1 + bf
// ---------------------------------------------------------------------------
__global__ void final_k(const float* __restrict__ Y,
                        const float* __restrict__ Wf0,
                        const float* __restrict__ Wf1,
                        const float* __restrict__ bf,
                        float* __restrict__ out) {
    int warp = threadIdx.x >> 5;
    int lane = threadIdx.x & 31;
    int node = blockIdx.x * (blockDim.x >> 5) + warp;
    if (node >= NN) return;

    float a0 = 0.f, a1 = 0.f, a2 = 0.f;
    for (int k = lane; k < HH; k += 32) {
        float yv = Y[(size_t)node * HH + k];
        float tv = g_T[(size_t)node * HH + k];
        a0 += yv * Wf0[k * 3 + 0] + tv * Wf1[k * 3 + 0];
        a1 += yv * Wf0[k * 3 + 1] + tv * Wf1[k * 3 + 1];
        a2 += yv * Wf0[k * 3 + 2] + tv * Wf1[k * 3 + 2];
    }
#pragma unroll
    for (int o = 16; o > 0; o >>= 1) {
        a0 += __shfl_xor_sync(0xffffffffu, a0, o);
        a1 += __shfl_xor_sync(0xffffffffu, a1, o);
        a2 += __shfl_xor_sync(0xffffffffu, a2, o);
    }
    if (lane == 0) {
        out[node * 3 + 0] = a0 + bf[0];
        out[node * 3 + 1] = a1 + bf[1];
        out[node * 3 + 2] = a2 + bf[2];
    }
}

// ---------------------------------------------------------------------------
// Launch
// ---------------------------------------------------------------------------
extern "C" void kernel_launch(void* const* d_in, const int* in_sizes, int n_in,
                              void* d_out, int out_size) {
    const float* x   = (const float*)d_in[0];
    const int*   ei  = (const int*)d_in[1];
    const float* Wi0 = (const float*)d_in[2];
    const float* Wi1 = (const float*)d_in[3];
    const float* bi  = (const float*)d_in[4];
    const float* Wr0 = (const float*)d_in[5];
    const float* Wr1 = (const float*)d_in[6];
    const float* br  = (const float*)d_in[7];
    const float* Wf0 = (const float*)d_in[8];
    const float* Wf1 = (const float*)d_in[9];
    const float* bf  = (const float*)d_in[10];

    float* out = (float*)d_out;
    float* Y   = out + (size_t)NN * 3;

    const int* row = ei;
    const int* col = ei + EE;

    float* dH = nullptr;
    cudaGetSymbolAddress((void**)&dH, g_H);

    cudaFuncSetAttribute(gemm_mma_k<0>, cudaFuncAttributeMaxDynamicSharedMemorySize, GEMM_SMEM);
    cudaFuncSetAttribute(gemm_mma_k<1>, cudaFuncAttributeMaxDynamicSharedMemorySize, GEMM_SMEM);

    const int nTB = (NN + 255) / 256;
    const int eTB = (EE + 255) / 256;
    const int nb  = (NN + SCAN_B - 1) / SCAN_B;

    // --- graph setup: degree, coefficients, CSR ---
    zero_k<<<nTB, 256>>>();
    degree_k<<<eTB, 256>>>(row);
    maxdeg_k<<<nTB, 256>>>();
    coeff_k<<<nTB, 256>>>();
    scan_block_k<<<nb, SCAN_B>>>();
    scan_sums_k<<<1, 64>>>(nb);
    scan_add_k<<<nb, SCAN_B>>>();
    scatter_k<<<eTB, 256>>>(row, col);

    // --- input layer ---
    agg3_k<<<nTB, 256>>>(x);
    input_gemm_k<<<400, 256>>>(x, Wi0, Wi1, bi, Y);

    // --- residual blocks (pipelined tf32 mma.sync GEMMs) ---
    dim3 gg((NN + 127) / 128, 2);
    for (int i = 0; i < 3; i++) {
        const float* W0a = Wr0 + (size_t)(2 * i) * HH * HH;
        const float* W1a = Wr1 + (size_t)(2 * i) * HH * HH;
        const float* ba  = br  + (size_t)(2 * i) * HH;
        const float* W0b = Wr0 + (size_t)(2 * i + 1) * HH * HH;
        const float* W1b = Wr1 + (size_t)(2 * i + 1) * HH * HH;
        const float* bb  = br  + (size_t)(2 * i + 1) * HH;

        agg256_k<<<NN, 256>>>(Y);
        gemm_mma_k<0><<<gg, 256, GEMM_SMEM>>>(Y, W0a, W1a, ba, dH, nullptr);
        agg256_k<<<NN, 256>>>(dH);
        gemm_mma_k<1><<<gg, 256, GEMM_SMEM>>>(dH, W0b, W1b, bb, Y, Y);
    }

    // --- final layer ---
    agg256_k<<<NN, 256>>>(Y);
    final_k<<<(NN + 3) / 4, 128>>>(Y, Wf0, Wf1, bf, out);
}